// round 14
// baseline (speedup 1.0000x reference)
#include <cuda_runtime.h>
#include <cuda_fp16.h>
#include <stdint.h>

// Flash attention, B=32, LQ=LK=2048, D=128, fp32 in/out. HMMA path.
// Mask: 4-byte elems (bool promoted); nonzero = masked. score=(q.k)*sqrt(128).
// QK^T: fp16 hi/lo 3-term MMA. PV: single-term fp16 (rel_err ~2.1e-4).
// R13: warp-specialized fill. 8 compute warps + 1 fill warp; 3-stage K+V ring
// guarded by named barriers (FULL ids 1-3, EMPTY ids 4-6, count 288).
// Compute warps share NO __syncthreads in the mainloop -> they drift and
// overlap QK (tensor) with softmax (ALU) across warps on each SMSP.

namespace {

constexpr int B_   = 32;
constexpr int LQ_  = 2048;
constexpr int LK_  = 2048;
constexpr int DH   = 128;
constexpr int BR   = 128;
constexpr int BC   = 64;
constexpr int NTH  = 288;             // 8 compute warps + 1 fill warp
constexpr int NIT  = LK_ / BC;
constexpr int RSB  = 272;             // 128 fp16 + 16B pad

constexpr int PLANE = BC * RSB;       // 17408 B
constexpr int STGSZ = 3 * PLANE;      // K hi + K lo + V per stage: 52224
constexpr int NSTG  = 3;
constexpr int SM_STG = 0;             // 3 stages: 156672
constexpr int SM_MSK = NSTG * STGSZ;
constexpr int MROW  = 68;
constexpr int SM_TOT = SM_MSK + BR * MROW;   // 165376 B

// Q prologue staging overlays the stage region (69632 <= 156672)
constexpr int SM_QHI = 0;
constexpr int SM_QLO = BR * RSB;

__device__ __half g_khi[(size_t)B_ * LK_ * DH];
__device__ __half g_klo[(size_t)B_ * LK_ * DH];
__device__ __half g_vh [(size_t)B_ * LK_ * DH];

__device__ __forceinline__ uint32_t smem_u32(const void* p) {
    return (uint32_t)__cvta_generic_to_shared(p);
}
__device__ __forceinline__ void cp16(uint32_t dst, const void* src) {
    asm volatile("cp.async.cg.shared.global [%0], [%1], 16;" :: "r"(dst), "l"(src));
}
#define CP_COMMIT() asm volatile("cp.async.commit_group;")

__device__ __forceinline__ void bar_sync_n(int id, int cnt) {
    asm volatile("bar.sync %0, %1;" :: "r"(id), "r"(cnt) : "memory");
}
__device__ __forceinline__ void bar_arrive_n(int id, int cnt) {
    asm volatile("bar.arrive %0, %1;" :: "r"(id), "r"(cnt) : "memory");
}

__device__ __forceinline__ void ldsm4(uint32_t r[4], uint32_t a) {
    asm volatile("ldmatrix.sync.aligned.m8n8.x4.shared.b16 {%0,%1,%2,%3}, [%4];"
                 : "=r"(r[0]), "=r"(r[1]), "=r"(r[2]), "=r"(r[3]) : "r"(a));
}
__device__ __forceinline__ void ldsm4t(uint32_t r[4], uint32_t a) {
    asm volatile("ldmatrix.sync.aligned.m8n8.x4.trans.shared.b16 {%0,%1,%2,%3}, [%4];"
                 : "=r"(r[0]), "=r"(r[1]), "=r"(r[2]), "=r"(r[3]) : "r"(a));
}
__device__ __forceinline__ void mma_f16(float d[4], const uint32_t a[4], uint32_t b0, uint32_t b1) {
    asm volatile("mma.sync.aligned.m16n8k16.row.col.f32.f16.f16.f32 "
                 "{%0,%1,%2,%3}, {%4,%5,%6,%7}, {%8,%9}, {%0,%1,%2,%3};"
                 : "+f"(d[0]), "+f"(d[1]), "+f"(d[2]), "+f"(d[3])
                 : "r"(a[0]), "r"(a[1]), "r"(a[2]), "r"(a[3]), "r"(b0), "r"(b1));
}
__device__ __forceinline__ float ex2f(float x) {
    float y; asm("ex2.approx.f32 %0, %1;" : "=f"(y) : "f"(x)); return y;
}
__device__ __forceinline__ uint32_t bits2h(__half2 h) {
    uint32_t u; __builtin_memcpy(&u, &h, 4); return u;
}
__device__ __forceinline__ void split_store_h(float4 f, char* ph, char* pl) {
    __half h0 = __float2half_rn(f.x);
    __half h1 = __float2half_rn(f.y);
    __half h2 = __float2half_rn(f.z);
    __half h3 = __float2half_rn(f.w);
    *(__half2*)(ph)     = __halves2half2(h0, h1);
    *(__half2*)(ph + 4) = __halves2half2(h2, h3);
    __half l0 = __float2half_rn(f.x - __half2float(h0));
    __half l1 = __float2half_rn(f.y - __half2float(h1));
    __half l2 = __float2half_rn(f.z - __half2float(h2));
    __half l3 = __float2half_rn(f.w - __half2float(h3));
    *(__half2*)(pl)     = __halves2half2(l0, l1);
    *(__half2*)(pl + 4) = __halves2half2(l2, l3);
}
__device__ __forceinline__ uint32_t pack_h2(float x, float y) {
    return bits2h(__halves2half2(__float2half_rn(x), __float2half_rn(y)));
}

__global__ void __launch_bounds__(256, 4)
conv_kernel(const float* __restrict__ kg, const float* __restrict__ vg)
{
    size_t i4 = ((size_t)blockIdx.x * 256 + threadIdx.x) * 4;
    float4 fk = *(const float4*)(kg + i4);
    split_store_h(fk, (char*)(g_khi + i4), (char*)(g_klo + i4));
    float4 fv = *(const float4*)(vg + i4);
    *(__half2*)(g_vh + i4)     = __halves2half2(__float2half_rn(fv.x), __float2half_rn(fv.y));
    *(__half2*)(g_vh + i4 + 2) = __halves2half2(__float2half_rn(fv.z), __float2half_rn(fv.w));
}

__global__ void __launch_bounds__(NTH, 1)
fa_r13_kernel(const float* __restrict__ qg, const uint32_t* __restrict__ mg,
              float* __restrict__ og)
{
    extern __shared__ char smem[];
    const int tid  = threadIdx.x;
    const int lane = tid & 31;
    const int warp = tid >> 5;
    const int b    = blockIdx.y;
    const int q0   = blockIdx.x * BR;

    const float K2  = 16.3222312f;   // sqrt(128) * log2(e)
    const float NEG = -1e30f;
    const uint32_t sm0 = smem_u32(smem);

    // ---- prologue: Q tile -> fp16 hi/lo smem (overlays stage region) ----
    {
        const float* qp = qg + ((size_t)b * LQ_ + q0) * DH;
        for (int idx = tid; idx < 4096; idx += NTH) {
            int row = idx >> 5, c4 = idx & 31;
            float4 f = *(const float4*)(qp + (size_t)row * DH + c4 * 4);
            split_store_h(f, smem + SM_QHI + row * RSB + c4 * 8,
                             smem + SM_QLO + row * RSB + c4 * 8);
        }
    }
    __syncthreads();

    uint32_t qa_hi[8][4], qa_lo[8][4];
    if (warp < 8) {
        uint32_t base = sm0 + (uint32_t)((warp * 16 + (lane & 15)) * RSB + (lane >> 4) * 16);
        #pragma unroll
        for (int kb = 0; kb < 8; ++kb) {
            ldsm4(qa_hi[kb], base + SM_QHI + kb * 32);
            ldsm4(qa_lo[kb], base + SM_QLO + kb * 32);
        }
    }
    __syncthreads();   // Q smem dead; stage region may be filled now

    if (warp == 8) {
        // =================== FILL WARP ===================
        const size_t kvoff0 = (size_t)b * LK_ * DH;
        auto fill_stage = [&](int j, int sj) {
            size_t off = kvoff0 + (size_t)j * BC * DH;
            uint32_t dstb = sm0 + (uint32_t)(SM_STG + sj * STGSZ);
            #pragma unroll
            for (int i = 0; i < 96; ++i) {
                int e = lane + i * 32;            // 0..3071
                int p = e >> 10, r = (e >> 4) & 63, c = e & 15;
                const __half* src = (p == 0 ? g_khi : p == 1 ? g_klo : g_vh)
                                    + off + (size_t)r * DH + c * 8;
                cp16(dstb + (uint32_t)(p * PLANE + r * RSB + c * 16), src);
            }
        };

        fill_stage(0, 0); CP_COMMIT();
        fill_stage(1, 1); CP_COMMIT();

        #pragma unroll 1
        for (int kt = 0; kt < NIT; ++kt) {
            const int j = kt + 2;
            if (j < NIT) {
                const int sj = j - (j / 3) * 3;
                if (j >= 3) bar_sync_n(4 + sj, NTH);   // wait EMPTY(sj)
                fill_stage(j, sj);
                CP_COMMIT();
                asm volatile("cp.async.wait_group 2;");
            } else if (kt + 1 < NIT) {
                asm volatile("cp.async.wait_group 1;");
            } else {
                asm volatile("cp.async.wait_group 0;");
            }
            bar_arrive_n(1 + (kt - (kt / 3) * 3), NTH);   // FULL(kt%3)
        }
        return;
    }

    // =================== COMPUTE WARPS (0..7) ===================
    const int mrow_w = warp * 16 + (lane >> 1);
    const uint32_t* mp_row = mg + (size_t)b * LQ_ * LK_ + (size_t)(q0 + mrow_w) * LK_
                                + (size_t)(lane & 1) * 32;
    uint32_t pk[8];
    auto ldgm = [&](int kt2) {
        const uint32_t* mp = mp_row + (size_t)kt2 * BC;
        #pragma unroll
        for (int j = 0; j < 8; ++j) {
            uint4 m = *(const uint4*)(mp + j * 4);
            pk[j] = (m.x ? 1u : 0u) | ((m.y ? 1u : 0u) << 8) |
                    ((m.z ? 1u : 0u) << 16) | ((m.w ? 1u : 0u) << 24);
        }
    };
    ldgm(0);

    float acc[16][4];
    #pragma unroll
    for (int j = 0; j < 16; ++j) { acc[j][0]=0.f; acc[j][1]=0.f; acc[j][2]=0.f; acc[j][3]=0.f; }
    float m0r = NEG, m1r = NEG, l0r = 0.f, l1r = 0.f;

    const int r0l = warp * 16 + (lane >> 2);
    const uint32_t kf_lane = (uint32_t)((lane & 7) * RSB + (lane >> 3) * 16);
    const uint32_t vf_lane = (uint32_t)((lane & 15) * RSB + (lane >> 4) * 16);
    char* mskw = smem + SM_MSK + mrow_w * MROW + (lane & 1) * 32;
    const char* mrd0 = smem + SM_MSK + r0l * MROW;
    const char* mrd1 = mrd0 + 8 * MROW;

    int st = 0;
    #pragma unroll 1
    for (int kt = 0; kt < NIT; ++kt) {
        bar_sync_n(1 + st, NTH);           // wait FULL(st): K(kt)+V(kt) ready

        // stage mask(kt) (warp-local), prefetch mask(kt+1)
        #pragma unroll
        for (int j = 0; j < 8; ++j) *(uint32_t*)(mskw + j * 4) = pk[j];
        __syncwarp();
        if (kt + 1 < NIT) ldgm(kt + 1);

        const uint32_t stg = sm0 + (uint32_t)(SM_STG + st * STGSZ);
        const uint32_t kfb = stg + kf_lane;              // K hi; +PLANE = K lo
        const uint32_t vfb = stg + 2 * PLANE + vf_lane;  // V

        // ---- S = Q K^T (fp16 hi/lo, 3 terms) ----
        float s[8][4];
        #pragma unroll
        for (int nb = 0; nb < 8; ++nb) { s[nb][0]=0.f; s[nb][1]=0.f; s[nb][2]=0.f; s[nb][3]=0.f; }
        #pragma unroll
        for (int kp2 = 0; kp2 < 4; ++kp2) {
            const int kb0 = 2 * kp2, kb1 = 2 * kp2 + 1;
            #pragma unroll
            for (int nbp = 0; nbp < 4; ++nbp) {
                const int n0 = 2 * nbp, n1 = 2 * nbp + 1;
                const uint32_t ka0 = kfb + (uint32_t)(n0 * 8 * RSB + kp2 * 64);
                const uint32_t ka1 = kfb + (uint32_t)(n1 * 8 * RSB + kp2 * 64);
                uint32_t bh0[4], bh1[4];
                ldsm4(bh0, ka0);
                ldsm4(bh1, ka1);
                mma_f16(s[n0], qa_hi[kb0], bh0[0], bh0[1]);
                mma_f16(s[n1], qa_hi[kb0], bh1[0], bh1[1]);
                mma_f16(s[n0], qa_lo[kb0], bh0[0], bh0[1]);
                mma_f16(s[n1], qa_lo[kb0], bh1[0], bh1[1]);
                mma_f16(s[n0], qa_hi[kb1], bh0[2], bh0[3]);
                mma_f16(s[n1], qa_hi[kb1], bh1[2], bh1[3]);
                mma_f16(s[n0], qa_lo[kb1], bh0[2], bh0[3]);
                mma_f16(s[n1], qa_lo[kb1], bh1[2], bh1[3]);
                ldsm4(bh0, ka0 + PLANE);
                ldsm4(bh1, ka1 + PLANE);
                mma_f16(s[n0], qa_hi[kb0], bh0[0], bh0[1]);
                mma_f16(s[n1], qa_hi[kb0], bh1[0], bh1[1]);
                mma_f16(s[n0], qa_hi[kb1], bh0[2], bh0[3]);
                mma_f16(s[n1], qa_hi[kb1], bh1[2], bh1[3]);
            }
        }

        // ---- mask + scale (log2 domain), online softmax ----
        float tm0 = NEG, tm1 = NEG;
        #pragma unroll
        for (int nb = 0; nb < 8; ++nb) {
            int c = (nb << 3) + ((lane & 3) << 1);
            uint32_t mm0 = *(const unsigned short*)(mrd0 + c);
            uint32_t mm1 = *(const unsigned short*)(mrd1 + c);
            s[nb][0] = (mm0 & 0xff) ? NEG : s[nb][0] * K2;
            s[nb][1] = (mm0 >> 8)   ? NEG : s[nb][1] * K2;
            s[nb][2] = (mm1 & 0xff) ? NEG : s[nb][2] * K2;
            s[nb][3] = (mm1 >> 8)   ? NEG : s[nb][3] * K2;
            tm0 = fmaxf(tm0, fmaxf(s[nb][0], s[nb][1]));
            tm1 = fmaxf(tm1, fmaxf(s[nb][2], s[nb][3]));
        }
        tm0 = fmaxf(tm0, __shfl_xor_sync(0xffffffffu, tm0, 1));
        tm0 = fmaxf(tm0, __shfl_xor_sync(0xffffffffu, tm0, 2));
        tm1 = fmaxf(tm1, __shfl_xor_sync(0xffffffffu, tm1, 1));
        tm1 = fmaxf(tm1, __shfl_xor_sync(0xffffffffu, tm1, 2));

        float mn0 = fmaxf(m0r, tm0), mn1 = fmaxf(m1r, tm1);
        float a0 = ex2f(m0r - mn0),  a1 = ex2f(m1r - mn1);
        float k0 = (mn0 > NEG) ? 1.f : 0.f;
        float k1 = (mn1 > NEG) ? 1.f : 0.f;

        float sum0 = 0.f, sum1 = 0.f;
        #pragma unroll
        for (int nb = 0; nb < 8; ++nb) {
            s[nb][0] = ex2f(s[nb][0] - mn0) * k0;
            s[nb][1] = ex2f(s[nb][1] - mn0) * k0;
            s[nb][2] = ex2f(s[nb][2] - mn1) * k1;
            s[nb][3] = ex2f(s[nb][3] - mn1) * k1;
            sum0 += s[nb][0] + s[nb][1];
            sum1 += s[nb][2] + s[nb][3];
        }
        sum0 += __shfl_xor_sync(0xffffffffu, sum0, 1);
        sum0 += __shfl_xor_sync(0xffffffffu, sum0, 2);
        sum1 += __shfl_xor_sync(0xffffffffu, sum1, 1);
        sum1 += __shfl_xor_sync(0xffffffffu, sum1, 2);
        l0r = l0r * a0 + sum0;
        l1r = l1r * a1 + sum1;
        m0r = mn0; m1r = mn1;

        if (__ballot_sync(0xffffffffu, (a0 != 1.f) || (a1 != 1.f))) {
            #pragma unroll
            for (int j = 0; j < 16; ++j) {
                acc[j][0] *= a0; acc[j][1] *= a0; acc[j][2] *= a1; acc[j][3] *= a1;
            }
        }

        // ---- O += P V (single-term fp16) ----
        #pragma unroll
        for (int kb = 0; kb < 4; ++kb) {
            uint32_t ph[4];
            ph[0] = pack_h2(s[2*kb][0],   s[2*kb][1]);
            ph[1] = pack_h2(s[2*kb][2],   s[2*kb][3]);
            ph[2] = pack_h2(s[2*kb+1][0], s[2*kb+1][1]);
            ph[3] = pack_h2(s[2*kb+1][2], s[2*kb+1][3]);
            uint32_t va = vfb + (uint32_t)(kb * 16 * RSB);
            #pragma unroll
            for (int jp = 0; jp < 8; ++jp) {
                uint32_t bh[4];
                ldsm4t(bh, va + jp * 32);
                mma_f16(acc[2*jp],   ph, bh[0], bh[1]);
                mma_f16(acc[2*jp+1], ph, bh[2], bh[3]);
            }
        }

        bar_arrive_n(4 + st, NTH);         // EMPTY(st): stage reusable
        st = (st == 2) ? 0 : st + 1;
    }

    // ---- epilogue ----
    float inv0 = (l0r > 0.f) ? (1.0f / l0r) : 0.f;
    float inv1 = (l1r > 0.f) ? (1.0f / l1r) : 0.f;
    const size_t gr0 = (size_t)b * LQ_ + q0 + r0l;
    const size_t gr1 = gr0 + 8;
    #pragma unroll
    for (int j = 0; j < 16; ++j) {
        int c = (j << 3) + ((lane & 3) << 1);
        float2 o0 = make_float2(acc[j][0] * inv0, acc[j][1] * inv0);
        float2 o1 = make_float2(acc[j][2] * inv1, acc[j][3] * inv1);
        *(float2*)(og + gr0 * DH + c) = o0;
        *(float2*)(og + gr1 * DH + c) = o1;
    }
}

} // namespace

extern "C" void kernel_launch(void* const* d_in, const int* in_sizes, int n_in,
                              void* d_out, int out_size) {
    const float* q = (const float*)d_in[0];
    const float* k = (const float*)d_in[1];
    const float* v = (const float*)d_in[2];
    const uint32_t* mask = (const uint32_t*)d_in[3];
    float* out = (float*)d_out;
    (void)in_sizes; (void)n_in; (void)out_size;

    conv_kernel<<<8192, 256>>>(k, v);

    cudaFuncSetAttribute(fa_r13_kernel, cudaFuncAttributeMaxDynamicSharedMemorySize, SM_TOT);
    dim3 grid(LQ_ / BR, B_);
    fa_r13_kernel<<<grid, NTH, SM_TOT>>>(q, mask, out);
}

// round 15
// speedup vs baseline: 1.4976x; 1.4976x over previous
#include <cuda_runtime.h>
#include <cuda_fp16.h>
#include <stdint.h>

// Flash attention, B=32, LQ=LK=2048, D=128, fp32 in/out. HMMA path.
// Mask: 4-byte elems (bool promoted); nonzero = masked. score=(q.k)*sqrt(128).
// QK^T: fp16 hi/lo 3-term MMA (K2 pre-folded into Q). PV: single-term fp16.
// R14 = R11 minus additive overhead: K2 folded into Q split, dead-row kill via
// msub=+BIG (ex2 underflow), single-instr f16x2 packing, PV ldsm preload.

namespace {

constexpr int B_   = 32;
constexpr int LQ_  = 2048;
constexpr int LK_  = 2048;
constexpr int DH   = 128;
constexpr int BR   = 128;
constexpr int BC   = 64;
constexpr int NTH  = 256;
constexpr int NIT  = LK_ / BC;
constexpr int RSB  = 272;             // 128 fp16 + 16B pad

constexpr int PLANE = BC * RSB;       // 17408 B
constexpr int KSTG  = 2 * PLANE;      // K hi+lo stage
constexpr int SM_K  = 0;              // 2 stages: 69632
constexpr int SM_V  = 2 * KSTG;       // V: 3 stages x 1 fp16 plane
constexpr int SM_MSK = SM_V + 3 * PLANE;
constexpr int MROW  = 68;
constexpr int MSKSTG = BR * MROW;     // x2 stages
constexpr int SM_TOT = SM_MSK + 2 * MSKSTG;   // 139264 B

constexpr int SM_QHI = 0;             // prologue overlay on K region
constexpr int SM_QLO = BR * RSB;

__device__ __half g_khi[(size_t)B_ * LK_ * DH];
__device__ __half g_klo[(size_t)B_ * LK_ * DH];
__device__ __half g_vh [(size_t)B_ * LK_ * DH];

__device__ __forceinline__ uint32_t smem_u32(const void* p) {
    return (uint32_t)__cvta_generic_to_shared(p);
}
__device__ __forceinline__ void cp16(uint32_t dst, const void* src) {
    asm volatile("cp.async.cg.shared.global [%0], [%1], 16;" :: "r"(dst), "l"(src));
}
#define CP_COMMIT() asm volatile("cp.async.commit_group;")
#define CP_WAIT0()  asm volatile("cp.async.wait_group 0;")

__device__ __forceinline__ void ldsm4(uint32_t r[4], uint32_t a) {
    asm volatile("ldmatrix.sync.aligned.m8n8.x4.shared.b16 {%0,%1,%2,%3}, [%4];"
                 : "=r"(r[0]), "=r"(r[1]), "=r"(r[2]), "=r"(r[3]) : "r"(a));
}
__device__ __forceinline__ void ldsm4t(uint32_t r[4], uint32_t a) {
    asm volatile("ldmatrix.sync.aligned.m8n8.x4.trans.shared.b16 {%0,%1,%2,%3}, [%4];"
                 : "=r"(r[0]), "=r"(r[1]), "=r"(r[2]), "=r"(r[3]) : "r"(a));
}
__device__ __forceinline__ void mma_f16(float d[4], const uint32_t a[4], uint32_t b0, uint32_t b1) {
    asm volatile("mma.sync.aligned.m16n8k16.row.col.f32.f16.f16.f32 "
                 "{%0,%1,%2,%3}, {%4,%5,%6,%7}, {%8,%9}, {%0,%1,%2,%3};"
                 : "+f"(d[0]), "+f"(d[1]), "+f"(d[2]), "+f"(d[3])
                 : "r"(a[0]), "r"(a[1]), "r"(a[2]), "r"(a[3]), "r"(b0), "r"(b1));
}
__device__ __forceinline__ float ex2f(float x) {
    float y; asm("ex2.approx.f32 %0, %1;" : "=f"(y) : "f"(x)); return y;
}
// one-instruction pack: f32 pair -> f16x2
__device__ __forceinline__ uint32_t pack_h2(float x, float y) {
    uint32_t r;
    asm("cvt.rn.f16x2.f32 %0, %1, %2;" : "=r"(r) : "f"(y), "f"(x));
    return r;
}
// fp16 hi/lo split with pre-scale: (f*scale) -> hi fp16, lo fp16 residual
__device__ __forceinline__ void split_store_hs(float4 f, float sc, char* ph, char* pl) {
    float x = f.x * sc, y = f.y * sc, z = f.z * sc, w = f.w * sc;
    __half h0 = __float2half_rn(x);
    __half h1 = __float2half_rn(y);
    __half h2 = __float2half_rn(z);
    __half h3 = __float2half_rn(w);
    *(__half2*)(ph)     = __halves2half2(h0, h1);
    *(__half2*)(ph + 4) = __halves2half2(h2, h3);
    __half l0 = __float2half_rn(x - __half2float(h0));
    __half l1 = __float2half_rn(y - __half2float(h1));
    __half l2 = __float2half_rn(z - __half2float(h2));
    __half l3 = __float2half_rn(w - __half2float(h3));
    *(__half2*)(pl)     = __halves2half2(l0, l1);
    *(__half2*)(pl + 4) = __halves2half2(l2, l3);
}

__global__ void __launch_bounds__(256, 4)
conv_kernel(const float* __restrict__ kg, const float* __restrict__ vg)
{
    size_t i4 = ((size_t)blockIdx.x * 256 + threadIdx.x) * 4;
    float4 fk = *(const float4*)(kg + i4);
    split_store_hs(fk, 1.0f, (char*)(g_khi + i4), (char*)(g_klo + i4));
    float4 fv = *(const float4*)(vg + i4);
    *(__half2*)(g_vh + i4)     = __halves2half2(__float2half_rn(fv.x), __float2half_rn(fv.y));
    *(__half2*)(g_vh + i4 + 2) = __halves2half2(__float2half_rn(fv.z), __float2half_rn(fv.w));
}

__global__ void __launch_bounds__(NTH, 1)
fa_r14_kernel(const float* __restrict__ qg, const uint32_t* __restrict__ mg,
              float* __restrict__ og)
{
    extern __shared__ char smem[];
    const int tid  = threadIdx.x;
    const int lane = tid & 31;
    const int warp = tid >> 5;
    const int b    = blockIdx.y;
    const int q0   = blockIdx.x * BR;

    const float K2  = 16.3222312f;   // sqrt(128) * log2(e), folded into Q
    const float NEG = -1e30f;
    const float BIG = 3e38f;
    const uint32_t sm0 = smem_u32(smem);

    // ---- prologue: Q tile * K2 -> fp16 hi/lo smem (overlays K buffers) ----
    {
        const float* qp = qg + ((size_t)b * LQ_ + q0) * DH;
        #pragma unroll
        for (int i = 0; i < 16; ++i) {
            int idx = tid + i * NTH;
            int row = idx >> 5, c4 = idx & 31;
            float4 f = *(const float4*)(qp + (size_t)row * DH + c4 * 4);
            split_store_hs(f, K2, smem + SM_QHI + row * RSB + c4 * 8,
                                  smem + SM_QLO + row * RSB + c4 * 8);
        }
    }
    __syncthreads();

    uint32_t qa_hi[8][4], qa_lo[8][4];
    {
        uint32_t base = sm0 + (uint32_t)((warp * 16 + (lane & 15)) * RSB + (lane >> 4) * 16);
        #pragma unroll
        for (int kb = 0; kb < 8; ++kb) {
            ldsm4(qa_hi[kb], base + SM_QHI + kb * 32);
            ldsm4(qa_lo[kb], base + SM_QLO + kb * 32);
        }
    }
    __syncthreads();

    // ---- fill helpers ----
    const size_t kvoff0 = (size_t)b * LK_ * DH + (size_t)(tid & 15) * 8;
    auto fill_K = [&](int kt2) {
        size_t off = kvoff0 + (size_t)kt2 * BC * DH;
        uint32_t dst0 = sm0 + (uint32_t)(SM_K + (kt2 & 1) * KSTG + (tid & 15) * 16);
        #pragma unroll
        for (int i = 0; i < 8; ++i) {
            const int p = i >> 2;
            const int row = (i & 3) * 16 + (tid >> 4);
            const __half* src = (p == 0 ? g_khi : g_klo) + off + (size_t)row * DH;
            cp16(dst0 + (uint32_t)(p * PLANE + row * RSB), src);
        }
    };
    auto fill_V = [&](int kt2, int vst) {
        size_t off = kvoff0 + (size_t)kt2 * BC * DH;
        uint32_t dst0 = sm0 + (uint32_t)(SM_V + vst * PLANE + (tid & 15) * 16);
        #pragma unroll
        for (int i = 0; i < 4; ++i) {
            const int row = i * 16 + (tid >> 4);
            cp16(dst0 + (uint32_t)(row * RSB), g_vh + off + (size_t)row * DH);
        }
    };

    // ---- mask prefetch + warp-local smem stage ----
    const int mrow_w = warp * 16 + (lane >> 1);
    const uint32_t* mp_row = mg + (size_t)b * LQ_ * LK_ + (size_t)(q0 + mrow_w) * LK_
                                + (size_t)(lane & 1) * 32;
    uint32_t pk[8];
    auto ldgm = [&](int kt2) {
        const uint32_t* mp = mp_row + (size_t)kt2 * BC;
        #pragma unroll
        for (int j = 0; j < 8; ++j) {
            uint4 m = *(const uint4*)(mp + j * 4);
            pk[j] = (m.x ? 1u : 0u) | ((m.y ? 1u : 0u) << 8) |
                    ((m.z ? 1u : 0u) << 16) | ((m.w ? 1u : 0u) << 24);
        }
    };

    fill_K(0);
    fill_V(0, 0);
    CP_COMMIT();
    ldgm(0);

    float acc[16][4];
    #pragma unroll
    for (int j = 0; j < 16; ++j) { acc[j][0]=0.f; acc[j][1]=0.f; acc[j][2]=0.f; acc[j][3]=0.f; }
    float m0r = NEG, m1r = NEG, l0r = 0.f, l1r = 0.f;

    const int r0l = warp * 16 + (lane >> 2);
    const uint32_t kf_lane = (uint32_t)((lane & 7) * RSB + (lane >> 3) * 16);
    const uint32_t vf_lane = (uint32_t)((lane & 15) * RSB + (lane >> 4) * 16);
    char* mskw0 = smem + SM_MSK + mrow_w * MROW + (lane & 1) * 32;
    const char* mrd_base = smem + SM_MSK + r0l * MROW;

    float sA[8][4], sB[8][4];

    // ---- plain QK (kt = 0 only) ----
    auto qk_plain = [&](int kt, float (&sC)[8][4]) {
        const uint32_t kfb = sm0 + (uint32_t)(SM_K + (kt & 1) * KSTG) + kf_lane;
        #pragma unroll
        for (int nb = 0; nb < 8; ++nb) { sC[nb][0]=0.f; sC[nb][1]=0.f; sC[nb][2]=0.f; sC[nb][3]=0.f; }
        #pragma unroll
        for (int kp2 = 0; kp2 < 4; ++kp2) {
            const int kb0 = 2 * kp2, kb1 = 2 * kp2 + 1;
            #pragma unroll
            for (int nbp = 0; nbp < 4; ++nbp) {
                const int n0 = 2 * nbp, n1 = 2 * nbp + 1;
                const uint32_t ka0 = kfb + (uint32_t)(n0 * 8 * RSB + kp2 * 64);
                const uint32_t ka1 = kfb + (uint32_t)(n1 * 8 * RSB + kp2 * 64);
                uint32_t bh0[4], bh1[4];
                ldsm4(bh0, ka0);
                ldsm4(bh1, ka1);
                mma_f16(sC[n0], qa_hi[kb0], bh0[0], bh0[1]);
                mma_f16(sC[n1], qa_hi[kb0], bh1[0], bh1[1]);
                mma_f16(sC[n0], qa_lo[kb0], bh0[0], bh0[1]);
                mma_f16(sC[n1], qa_lo[kb0], bh1[0], bh1[1]);
                mma_f16(sC[n0], qa_hi[kb1], bh0[2], bh0[3]);
                mma_f16(sC[n1], qa_hi[kb1], bh1[2], bh1[3]);
                mma_f16(sC[n0], qa_lo[kb1], bh0[2], bh0[3]);
                mma_f16(sC[n1], qa_lo[kb1], bh1[2], bh1[3]);
                ldsm4(bh0, ka0 + PLANE);
                ldsm4(bh1, ka1 + PLANE);
                mma_f16(sC[n0], qa_hi[kb0], bh0[0], bh0[1]);
                mma_f16(sC[n1], qa_hi[kb0], bh1[0], bh1[1]);
                mma_f16(sC[n0], qa_hi[kb1], bh0[2], bh0[3]);
                mma_f16(sC[n1], qa_hi[kb1], bh1[2], bh1[3]);
            }
        }
    };

    // ---- fused: QK(kt) with softmax(kt-1) chunks interleaved ----
    auto fused = [&](int kt, float (&sC)[8][4], float (&s)[8][4]) {
        const uint32_t kfb = sm0 + (uint32_t)(SM_K + (kt & 1) * KSTG) + kf_lane;
        const char* mrd0 = mrd_base + ((kt - 1) & 1) * MSKSTG;
        const char* mrd1 = mrd0 + 8 * MROW;
        #pragma unroll
        for (int nb = 0; nb < 8; ++nb) { sC[nb][0]=0.f; sC[nb][1]=0.f; sC[nb][2]=0.f; sC[nb][3]=0.f; }
        float tm0 = NEG, tm1 = NEG;
        float ms0 = 0.f, ms1 = 0.f, a0 = 1.f, a1 = 1.f;
        float sum0 = 0.f, sum1 = 0.f;

        #pragma unroll
        for (int kp2 = 0; kp2 < 4; ++kp2) {
            const int kb0 = 2 * kp2, kb1 = 2 * kp2 + 1;
            #pragma unroll
            for (int nbp = 0; nbp < 4; ++nbp) {
                const int u  = kp2 * 4 + nbp;
                const int n0 = 2 * nbp, n1 = 2 * nbp + 1;
                const uint32_t ka0 = kfb + (uint32_t)(n0 * 8 * RSB + kp2 * 64);
                const uint32_t ka1 = kfb + (uint32_t)(n1 * 8 * RSB + kp2 * 64);
                uint32_t bh0[4], bh1[4];
                ldsm4(bh0, ka0);
                ldsm4(bh1, ka1);
                mma_f16(sC[n0], qa_hi[kb0], bh0[0], bh0[1]);
                mma_f16(sC[n1], qa_hi[kb0], bh1[0], bh1[1]);
                mma_f16(sC[n0], qa_lo[kb0], bh0[0], bh0[1]);
                mma_f16(sC[n1], qa_lo[kb0], bh1[0], bh1[1]);
                mma_f16(sC[n0], qa_hi[kb1], bh0[2], bh0[3]);
                mma_f16(sC[n1], qa_hi[kb1], bh1[2], bh1[3]);
                mma_f16(sC[n0], qa_lo[kb1], bh0[2], bh0[3]);
                mma_f16(sC[n1], qa_lo[kb1], bh1[2], bh1[3]);

                // -------- softmax(kt-1) chunk u ----
                if (u < 8) {
                    const int nb = u;
                    int c = (nb << 3) + ((lane & 3) << 1);
                    uint32_t mm0 = *(const unsigned short*)(mrd0 + c);
                    uint32_t mm1 = *(const unsigned short*)(mrd1 + c);
                    s[nb][0] = (mm0 & 0xff) ? NEG : s[nb][0];
                    s[nb][1] = (mm0 >> 8)   ? NEG : s[nb][1];
                    s[nb][2] = (mm1 & 0xff) ? NEG : s[nb][2];
                    s[nb][3] = (mm1 >> 8)   ? NEG : s[nb][3];
                    tm0 = fmaxf(tm0, fmaxf(s[nb][0], s[nb][1]));
                    tm1 = fmaxf(tm1, fmaxf(s[nb][2], s[nb][3]));
                } else if (u == 8) {
                    tm0 = fmaxf(tm0, __shfl_xor_sync(0xffffffffu, tm0, 1));
                    tm0 = fmaxf(tm0, __shfl_xor_sync(0xffffffffu, tm0, 2));
                    tm1 = fmaxf(tm1, __shfl_xor_sync(0xffffffffu, tm1, 1));
                    tm1 = fmaxf(tm1, __shfl_xor_sync(0xffffffffu, tm1, 2));
                    float mn0 = fmaxf(m0r, tm0), mn1 = fmaxf(m1r, tm1);
                    a0 = ex2f(m0r - mn0);  a1 = ex2f(m1r - mn1);
                    ms0 = (mn0 > NEG) ? mn0 : BIG;   // dead row -> p underflows to 0
                    ms1 = (mn1 > NEG) ? mn1 : BIG;
                    m0r = mn0; m1r = mn1;
                } else if (u <= 12) {
                    #pragma unroll
                    for (int q2 = 0; q2 < 2; ++q2) {
                        const int nb = 2 * (u - 9) + q2;
                        s[nb][0] = ex2f(s[nb][0] - ms0);
                        s[nb][1] = ex2f(s[nb][1] - ms0);
                        s[nb][2] = ex2f(s[nb][2] - ms1);
                        s[nb][3] = ex2f(s[nb][3] - ms1);
                        sum0 += s[nb][0] + s[nb][1];
                        sum1 += s[nb][2] + s[nb][3];
                    }
                } else if (u == 13) {
                    sum0 += __shfl_xor_sync(0xffffffffu, sum0, 1);
                    sum0 += __shfl_xor_sync(0xffffffffu, sum0, 2);
                    sum1 += __shfl_xor_sync(0xffffffffu, sum1, 1);
                    sum1 += __shfl_xor_sync(0xffffffffu, sum1, 2);
                    l0r = l0r * a0 + sum0;
                    l1r = l1r * a1 + sum1;
                } else if (u == 14) {
                    if (__ballot_sync(0xffffffffu, (a0 != 1.f) || (a1 != 1.f))) {
                        #pragma unroll
                        for (int j = 0; j < 8; ++j) {
                            acc[j][0] *= a0; acc[j][1] *= a0; acc[j][2] *= a1; acc[j][3] *= a1;
                        }
                    }
                } else {
                    if (__ballot_sync(0xffffffffu, (a0 != 1.f) || (a1 != 1.f))) {
                        #pragma unroll
                        for (int j = 8; j < 16; ++j) {
                            acc[j][0] *= a0; acc[j][1] *= a0; acc[j][2] *= a1; acc[j][3] *= a1;
                        }
                    }
                }
                // ------------------------------------

                ldsm4(bh0, ka0 + PLANE);
                ldsm4(bh1, ka1 + PLANE);
                mma_f16(sC[n0], qa_hi[kb0], bh0[0], bh0[1]);
                mma_f16(sC[n1], qa_hi[kb0], bh1[0], bh1[1]);
                mma_f16(sC[n0], qa_hi[kb1], bh0[2], bh0[3]);
                mma_f16(sC[n1], qa_hi[kb1], bh1[2], bh1[3]);
            }
        }
    };

    // ---- plain softmax (final tile) ----
    auto softmax_plain = [&](int ktp, float (&s)[8][4]) {
        const char* mrd0 = mrd_base + (ktp & 1) * MSKSTG;
        const char* mrd1 = mrd0 + 8 * MROW;
        float tm0 = NEG, tm1 = NEG;
        #pragma unroll
        for (int nb = 0; nb < 8; ++nb) {
            int c = (nb << 3) + ((lane & 3) << 1);
            uint32_t mm0 = *(const unsigned short*)(mrd0 + c);
            uint32_t mm1 = *(const unsigned short*)(mrd1 + c);
            s[nb][0] = (mm0 & 0xff) ? NEG : s[nb][0];
            s[nb][1] = (mm0 >> 8)   ? NEG : s[nb][1];
            s[nb][2] = (mm1 & 0xff) ? NEG : s[nb][2];
            s[nb][3] = (mm1 >> 8)   ? NEG : s[nb][3];
            tm0 = fmaxf(tm0, fmaxf(s[nb][0], s[nb][1]));
            tm1 = fmaxf(tm1, fmaxf(s[nb][2], s[nb][3]));
        }
        tm0 = fmaxf(tm0, __shfl_xor_sync(0xffffffffu, tm0, 1));
        tm0 = fmaxf(tm0, __shfl_xor_sync(0xffffffffu, tm0, 2));
        tm1 = fmaxf(tm1, __shfl_xor_sync(0xffffffffu, tm1, 1));
        tm1 = fmaxf(tm1, __shfl_xor_sync(0xffffffffu, tm1, 2));
        float mn0 = fmaxf(m0r, tm0), mn1 = fmaxf(m1r, tm1);
        float a0 = ex2f(m0r - mn0),  a1 = ex2f(m1r - mn1);
        float ms0 = (mn0 > NEG) ? mn0 : BIG;
        float ms1 = (mn1 > NEG) ? mn1 : BIG;
        float sum0 = 0.f, sum1 = 0.f;
        #pragma unroll
        for (int nb = 0; nb < 8; ++nb) {
            s[nb][0] = ex2f(s[nb][0] - ms0);
            s[nb][1] = ex2f(s[nb][1] - ms0);
            s[nb][2] = ex2f(s[nb][2] - ms1);
            s[nb][3] = ex2f(s[nb][3] - ms1);
            sum0 += s[nb][0] + s[nb][1];
            sum1 += s[nb][2] + s[nb][3];
        }
        sum0 += __shfl_xor_sync(0xffffffffu, sum0, 1);
        sum0 += __shfl_xor_sync(0xffffffffu, sum0, 2);
        sum1 += __shfl_xor_sync(0xffffffffu, sum1, 1);
        sum1 += __shfl_xor_sync(0xffffffffu, sum1, 2);
        l0r = l0r * a0 + sum0;
        l1r = l1r * a1 + sum1;
        m0r = mn0; m1r = mn1;
        #pragma unroll
        for (int j = 0; j < 16; ++j) {
            acc[j][0] *= a0; acc[j][1] *= a0; acc[j][2] *= a1; acc[j][3] *= a1;
        }
    };

    // ---- PV (single-term fp16, ldsm preloaded one step ahead) ----
    auto pv = [&](int ktp, float (&s)[8][4]) {
        const int vst = ktp - (ktp / 3) * 3;
        const uint32_t vfb = sm0 + (uint32_t)(SM_V + vst * PLANE) + vf_lane;
        uint32_t bh[4], bn[4];
        ldsm4t(bh, vfb);                       // preload (kb=0, jp=0)
        #pragma unroll
        for (int kb = 0; kb < 4; ++kb) {
            uint32_t ph[4];
            ph[0] = pack_h2(s[2*kb][0],   s[2*kb][1]);
            ph[1] = pack_h2(s[2*kb][2],   s[2*kb][3]);
            ph[2] = pack_h2(s[2*kb+1][0], s[2*kb+1][1]);
            ph[3] = pack_h2(s[2*kb+1][2], s[2*kb+1][3]);
            uint32_t va = vfb + (uint32_t)(kb * 16 * RSB);
            #pragma unroll
            for (int jp = 0; jp < 8; ++jp) {
                // preload next fragment before consuming current
                if (jp < 7) {
                    ldsm4t(bn, va + (jp + 1) * 32);
                } else if (kb < 3) {
                    ldsm4t(bn, vfb + (uint32_t)((kb + 1) * 16 * RSB));
                }
                mma_f16(acc[2*jp],   ph, bh[0], bh[1]);
                mma_f16(acc[2*jp+1], ph, bh[2], bh[3]);
                bh[0] = bn[0]; bh[1] = bn[1]; bh[2] = bn[2]; bh[3] = bn[3];
            }
        }
    };

    // ---- one iteration ----
    auto iter = [&](int kt, float (&sC)[8][4], float (&sP)[8][4]) {
        CP_WAIT0();
        __syncthreads();
        if (kt + 1 < NIT) {
            fill_K(kt + 1);
            int vw = kt + 1; vw -= (vw / 3) * 3;
            fill_V(kt + 1, vw);
        }
        CP_COMMIT();

        char* mw = mskw0 + (kt & 1) * MSKSTG;
        #pragma unroll
        for (int j = 0; j < 8; ++j) *(uint32_t*)(mw + j * 4) = pk[j];
        __syncwarp();
        if (kt + 1 < NIT) ldgm(kt + 1);

        if (kt == 0) {
            qk_plain(0, sC);
        } else {
            fused(kt, sC, sP);
            pv(kt - 1, sP);
        }
    };

    #pragma unroll 1
    for (int kt2 = 0; kt2 < NIT; kt2 += 2) {
        iter(kt2,     sA, sB);
        iter(kt2 + 1, sB, sA);
    }
    softmax_plain(NIT - 1, sB);
    pv(NIT - 1, sB);

    // ---- epilogue ----
    float inv0 = (l0r > 0.f) ? (1.0f / l0r) : 0.f;
    float inv1 = (l1r > 0.f) ? (1.0f / l1r) : 0.f;
    const size_t gr0 = (size_t)b * LQ_ + q0 + r0l;
    const size_t gr1 = gr0 + 8;
    #pragma unroll
    for (int j = 0; j < 16; ++j) {
        int c = (j << 3) + ((lane & 3) << 1);
        float2 o0 = make_float2(acc[j][0] * inv0, acc[j][1] * inv0);
        float2 o1 = make_float2(acc[j][2] * inv1, acc[j][3] * inv1);
        *(float2*)(og + gr0 * DH + c) = o0;
        *(float2*)(og + gr1 * DH + c) = o1;
    }
}

} // namespace

extern "C" void kernel_launch(void* const* d_in, const int* in_sizes, int n_in,
                              void* d_out, int out_size) {
    const float* q = (const float*)d_in[0];
    const float* k = (const float*)d_in[1];
    const float* v = (const float*)d_in[2];
    const uint32_t* mask = (const uint32_t*)d_in[3];
    float* out = (float*)d_out;
    (void)in_sizes; (void)n_in; (void)out_size;

    conv_kernel<<<8192, 256>>>(k, v);

    cudaFuncSetAttribute(fa_r14_kernel, cudaFuncAttributeMaxDynamicSharedMemorySize, SM_TOT);
    dim3 grid(LQ_ / BR, B_);
    fa_r14_kernel<<<grid, NTH, SM_TOT>>>(q, mask, out);
}